// round 5
// baseline (speedup 1.0000x reference)
#include <cuda_runtime.h>
#include <stdint.h>
#include <math.h>

#define NTOK 16384
#define HD   4096
#define NE   64
#define NP   6
#define TK   8

#define WARPS    16
#define TPW      4
#define TPB      64
#define NTHREADS 512

#define CHUNK_F      256                    // floats per token per chunk
#define CHUNK_FLOATS (TPB * CHUNK_F)        // 16384 floats = 64 KB
#define NCHUNK       (HD / CHUNK_F)         // 16

// smem layout (floats): xbuf[2][CHUNK_FLOATS] | comp[NP*HD] | cent | centn | cpart | cvec
#define XBUF_OFF   0
#define COMP_OFF   (2 * CHUNK_FLOATS)
#define CENT_OFF   (COMP_OFF + NP * HD)
#define CENTN_OFF  (CENT_OFF + NE * NP)
#define CPART_OFF  (CENTN_OFF + NE)
#define CVEC_OFF   (CPART_OFF + WARPS * NP)
#define SMEM_FLOATS (CVEC_OFF + NP)
#define SMEM_BYTES  (SMEM_FLOATS * 4)       // 231,576 B <= 232,448 max

#define FMA2(acc, a, b) \
    asm("fma.rn.f32x2 %0, %1, %2, %0;" : "+l"(acc) : "l"(a), "l"(b))

__device__ __forceinline__ uint32_t smem_u32(const void* p) {
    uint32_t a;
    asm("{ .reg .u64 t; cvta.to.shared.u64 t, %1; cvt.u32.u64 %0, t; }" : "=r"(a) : "l"(p));
    return a;
}

#define CP_ASYNC16(dst, src) \
    asm volatile("cp.async.cg.shared.global [%0], [%1], 16;" :: "r"(dst), "l"(src) : "memory")
#define CP_COMMIT() asm volatile("cp.async.commit_group;" ::: "memory")
#define CP_WAIT1()  asm volatile("cp.async.wait_group 1;" ::: "memory")
#define CP_WAIT0()  asm volatile("cp.async.wait_group 0;" ::: "memory")

__global__ void __launch_bounds__(NTHREADS, 1)
kdtree_router_kernel(const float* __restrict__ x,
                     const float* __restrict__ mean,
                     const float* __restrict__ comp,
                     const float* __restrict__ cent,
                     float* __restrict__ out)
{
    extern __shared__ __align__(128) float smem[];
    float* comp_s  = smem + COMP_OFF;
    float* cent_s  = smem + CENT_OFF;
    float* centn_s = smem + CENTN_OFF;
    float* cpart   = smem + CPART_OFF;
    float* cvec    = smem + CVEC_OFF;
    const uint32_t xs = smem_u32(smem + XBUF_OFF);

    const int tid  = threadIdx.x;
    const int lane = tid & 31;
    const int warp = tid >> 5;

    const float* xrow = x + (size_t)blockIdx.x * TPB * HD;

    // ---- stage chunk 0 immediately (DRAM busy during prologue) ----
    #pragma unroll
    for (int j = 0; j < 8; j++) {
        int idx = j * NTHREADS + tid;        // 0..4095 float4 slots
        int tt  = idx >> 6;                   // token in block
        int off = idx & 63;                   // float4 within 256-float chunk
        const float* src = xrow + (size_t)tt * HD + off * 4;
        CP_ASYNC16(xs + idx * 16, src);
    }
    CP_COMMIT();

    // ---- load PCA components + centroids into smem ----
    {
        const float4* cg = (const float4*)comp;
        float4* cs = (float4*)comp_s;
        for (int i = tid; i < NP * HD / 4; i += NTHREADS) cs[i] = cg[i];
        for (int i = tid; i < NE * NP; i += NTHREADS) cent_s[i] = cent[i];
    }
    __syncthreads();

    // ---- per-block constants: cvec[p] = mean . comp[p]; centroid norms ----
    {
        float a0=0.f,a1=0.f,a2=0.f,a3=0.f,a4=0.f,a5=0.f;
        #pragma unroll
        for (int j = 0; j < HD / (WARPS * 32); j++) {
            int h = warp * (HD / WARPS) + lane + j * 32;
            float m = __ldg(mean + h);
            a0 += m * comp_s[0*HD + h];
            a1 += m * comp_s[1*HD + h];
            a2 += m * comp_s[2*HD + h];
            a3 += m * comp_s[3*HD + h];
            a4 += m * comp_s[4*HD + h];
            a5 += m * comp_s[5*HD + h];
        }
        #pragma unroll
        for (int o = 16; o > 0; o >>= 1) {
            a0 += __shfl_xor_sync(0xffffffffu, a0, o);
            a1 += __shfl_xor_sync(0xffffffffu, a1, o);
            a2 += __shfl_xor_sync(0xffffffffu, a2, o);
            a3 += __shfl_xor_sync(0xffffffffu, a3, o);
            a4 += __shfl_xor_sync(0xffffffffu, a4, o);
            a5 += __shfl_xor_sync(0xffffffffu, a5, o);
        }
        if (lane == 0) {
            cpart[warp*NP+0]=a0; cpart[warp*NP+1]=a1; cpart[warp*NP+2]=a2;
            cpart[warp*NP+3]=a3; cpart[warp*NP+4]=a4; cpart[warp*NP+5]=a5;
        }
        if (tid < NE) {
            float s = 0.f;
            #pragma unroll
            for (int p = 0; p < NP; p++) { float c = cent_s[tid*NP + p]; s += c * c; }
            centn_s[tid] = s;
        }
    }
    __syncthreads();
    if (tid < NP) {
        float s = 0.f;
        #pragma unroll
        for (int w = 0; w < WARPS; w++) s += cpart[w*NP + tid];
        cvec[tid] = s;
    }
    __syncthreads();

    // ---- main loop: 16 chunks, double-buffered cp.async staging ----
    unsigned long long acc[TPW][NP];
    #pragma unroll
    for (int t = 0; t < TPW; t++)
        #pragma unroll
        for (int p = 0; p < NP; p++) acc[t][p] = 0ull;

    const ulonglong2* cu = (const ulonglong2*)comp_s;   // NP rows of 1024 ull2

    #pragma unroll 1
    for (int c = 0; c < NCHUNK; c++) {
        const int sc = c & 1;
        if (c + 1 < NCHUNK) {
            const int cn = c + 1;
            const uint32_t dbase = xs + (cn & 1) * (CHUNK_FLOATS * 4);
            #pragma unroll
            for (int j = 0; j < 8; j++) {
                int idx = j * NTHREADS + tid;
                int tt  = idx >> 6;
                int off = idx & 63;
                const float* src = xrow + (size_t)tt * HD + cn * CHUNK_F + off * 4;
                CP_ASYNC16(dbase + idx * 16, src);
            }
            CP_COMMIT();
            CP_WAIT1();          // chunk c's group complete (this thread)
        } else {
            CP_WAIT0();
        }
        __syncthreads();         // all threads' copies of chunk c visible

        // compute on chunk c: 2 half-iterations of 128 floats per token
        const ulonglong2* xb = (const ulonglong2*)(smem + XBUF_OFF + sc * CHUNK_FLOATS);
        #pragma unroll
        for (int i = 0; i < 2; i++) {
            const int ci = c * 64 + i * 32 + lane;       // ull2 index into comp row
            ulonglong2 c0 = cu[0*1024 + ci];
            ulonglong2 c1 = cu[1*1024 + ci];
            ulonglong2 c2 = cu[2*1024 + ci];
            ulonglong2 c3 = cu[3*1024 + ci];
            ulonglong2 c4 = cu[4*1024 + ci];
            ulonglong2 c5 = cu[5*1024 + ci];

            ulonglong2 v0 = xb[(warp*TPW + 0)*64 + i*32 + lane];
            ulonglong2 v1 = xb[(warp*TPW + 1)*64 + i*32 + lane];
            ulonglong2 v2 = xb[(warp*TPW + 2)*64 + i*32 + lane];
            ulonglong2 v3 = xb[(warp*TPW + 3)*64 + i*32 + lane];

            FMA2(acc[0][0], v0.x, c0.x); FMA2(acc[0][0], v0.y, c0.y);
            FMA2(acc[0][1], v0.x, c1.x); FMA2(acc[0][1], v0.y, c1.y);
            FMA2(acc[0][2], v0.x, c2.x); FMA2(acc[0][2], v0.y, c2.y);
            FMA2(acc[0][3], v0.x, c3.x); FMA2(acc[0][3], v0.y, c3.y);
            FMA2(acc[0][4], v0.x, c4.x); FMA2(acc[0][4], v0.y, c4.y);
            FMA2(acc[0][5], v0.x, c5.x); FMA2(acc[0][5], v0.y, c5.y);

            FMA2(acc[1][0], v1.x, c0.x); FMA2(acc[1][0], v1.y, c0.y);
            FMA2(acc[1][1], v1.x, c1.x); FMA2(acc[1][1], v1.y, c1.y);
            FMA2(acc[1][2], v1.x, c2.x); FMA2(acc[1][2], v1.y, c2.y);
            FMA2(acc[1][3], v1.x, c3.x); FMA2(acc[1][3], v1.y, c3.y);
            FMA2(acc[1][4], v1.x, c4.x); FMA2(acc[1][4], v1.y, c4.y);
            FMA2(acc[1][5], v1.x, c5.x); FMA2(acc[1][5], v1.y, c5.y);

            FMA2(acc[2][0], v2.x, c0.x); FMA2(acc[2][0], v2.y, c0.y);
            FMA2(acc[2][1], v2.x, c1.x); FMA2(acc[2][1], v2.y, c1.y);
            FMA2(acc[2][2], v2.x, c2.x); FMA2(acc[2][2], v2.y, c2.y);
            FMA2(acc[2][3], v2.x, c3.x); FMA2(acc[2][3], v2.y, c3.y);
            FMA2(acc[2][4], v2.x, c4.x); FMA2(acc[2][4], v2.y, c4.y);
            FMA2(acc[2][5], v2.x, c5.x); FMA2(acc[2][5], v2.y, c5.y);

            FMA2(acc[3][0], v3.x, c0.x); FMA2(acc[3][0], v3.y, c0.y);
            FMA2(acc[3][1], v3.x, c1.x); FMA2(acc[3][1], v3.y, c1.y);
            FMA2(acc[3][2], v3.x, c2.x); FMA2(acc[3][2], v3.y, c2.y);
            FMA2(acc[3][3], v3.x, c3.x); FMA2(acc[3][3], v3.y, c3.y);
            FMA2(acc[3][4], v3.x, c4.x); FMA2(acc[3][4], v3.y, c4.y);
            FMA2(acc[3][5], v3.x, c5.x); FMA2(acc[3][5], v3.y, c5.y);
        }
        __syncthreads();         // chunk c fully consumed before next overwrite
    }

    // ---- reduce across warp (butterfly leaves sums in all lanes) ----
    float pr[TPW][NP];
    #pragma unroll
    for (int t = 0; t < TPW; t++) {
        #pragma unroll
        for (int p = 0; p < NP; p++) {
            unsigned long long v = acc[t][p];
            float s = __uint_as_float((unsigned)(v & 0xffffffffull)) +
                      __uint_as_float((unsigned)(v >> 32));
            #pragma unroll
            for (int o = 16; o > 0; o >>= 1)
                s += __shfl_xor_sync(0xffffffffu, s, o);
            pr[t][p] = s - cvec[p];
        }
    }

    // ---- epilogue: distances, softmax over 64, top-8 ----
    float* out_idx = out;
    float* out_tp  = out + (size_t)NTOK * TK;
    float* out_pr  = out + 2 * (size_t)NTOK * TK;

    #pragma unroll 1
    for (int t = 0; t < TPW; t++) {
        const int tok = blockIdx.x * TPB + warp * TPW + t;
        float pn = 0.f;
        #pragma unroll
        for (int p = 0; p < NP; p++) pn += pr[t][p] * pr[t][p];

        const int e0 = lane, e1 = lane + 32;
        float dot0 = 0.f, dot1 = 0.f;
        #pragma unroll
        for (int p = 0; p < NP; p++) {
            dot0 += pr[t][p] * cent_s[e0*NP + p];
            dot1 += pr[t][p] * cent_s[e1*NP + p];
        }
        float d20 = pn - 2.f*dot0 + centn_s[e0];
        float d21 = pn - 2.f*dot1 + centn_s[e1];
        float s0 = -sqrtf(fmaxf(d20, 0.f));
        float s1 = -sqrtf(fmaxf(d21, 0.f));

        float m = fmaxf(s0, s1);
        #pragma unroll
        for (int o = 16; o > 0; o >>= 1)
            m = fmaxf(m, __shfl_xor_sync(0xffffffffu, m, o));
        float ex0 = expf(s0 - m);
        float ex1 = expf(s1 - m);
        float sum = ex0 + ex1;
        #pragma unroll
        for (int o = 16; o > 0; o >>= 1)
            sum += __shfl_xor_sync(0xffffffffu, sum, o);
        float p0 = ex0 / sum;
        float p1 = ex1 / sum;

        out_pr[(size_t)tok*NE + e0] = p0;
        out_pr[(size_t)tok*NE + e1] = p1;

        // top-8 via 8-round warp argmax; tie-break = lower index (jax.lax.top_k)
        unsigned long long k0 = ((unsigned long long)__float_as_uint(p0) << 32) | (unsigned)(NE-1 - e0);
        unsigned long long k1 = ((unsigned long long)__float_as_uint(p1) << 32) | (unsigned)(NE-1 - e1);
        float tsum = 0.f, myp = 0.f;
        int myi = 0;
        #pragma unroll
        for (int r = 0; r < TK; r++) {
            unsigned long long b = (k0 > k1) ? k0 : k1;
            #pragma unroll
            for (int o = 16; o > 0; o >>= 1) {
                unsigned long long v = __shfl_xor_sync(0xffffffffu, b, o);
                if (v > b) b = v;
            }
            int idx = NE-1 - (int)(b & 0xffull);
            float pv = __uint_as_float((unsigned)(b >> 32));
            tsum += pv;
            if (lane == r) { myp = pv; myi = idx; }
            if (idx == e0) k0 = 0ull;
            if (idx == e1) k1 = 0ull;
        }
        if (lane < TK) {
            out_idx[(size_t)tok*TK + lane] = (float)myi;
            out_tp [(size_t)tok*TK + lane] = myp / tsum;
        }
    }
}

extern "C" void kernel_launch(void* const* d_in, const int* in_sizes, int n_in,
                              void* d_out, int out_size)
{
    const float* x    = (const float*)d_in[0];
    const float* mean = (const float*)d_in[1];
    const float* comp = (const float*)d_in[2];
    const float* cent = (const float*)d_in[3];
    float* out = (float*)d_out;

    cudaFuncSetAttribute(kdtree_router_kernel,
                         cudaFuncAttributeMaxDynamicSharedMemorySize, SMEM_BYTES);
    kdtree_router_kernel<<<NTOK / TPB, NTHREADS, SMEM_BYTES>>>(x, mean, comp, cent, out);
}

// round 6
// speedup vs baseline: 1.0828x; 1.0828x over previous
#include <cuda_runtime.h>
#include <stdint.h>
#include <math.h>

#define NTOK 16384
#define HD   4096
#define NE   64
#define NP   6
#define TK   8

#define CWARPS   16                     // consumer warps (one 256-col slice each)
#define NTHREADS ((CWARPS + 1) * 32)    // 544: +1 producer warp
#define PROD_WARP CWARPS
#define TPB      64                     // tokens per block
#define SLICE    (HD / CWARPS)          // 256 columns per warp

#define STAGE_TOK   4
#define STAGE_BYTES (STAGE_TOK * HD * 4)   // 65536
#define NCHUNK      (TPB / STAGE_TOK)      // 16
#define STAGES      2
#define PDIST       2                      // prefetch distance in chunks

// smem byte offsets
#define XS_OFF    0
#define PART_OFF  (XS_OFF + STAGES * STAGE_BYTES)          // 131072
#define PART_SZ   ((TPB + 1) * NP * 32 * 4)                // 49920 (token 64 = mean proj)
#define CENT_OFF  (PART_OFF + PART_SZ)
#define CENTN_OFF (CENT_OFF + NE * NP * 4)
#define MBAR_OFF  ((CENTN_OFF + NE * 4 + 15) & ~15)
#define SMEM_BYTES (MBAR_OFF + 64)

#define FMA2(acc, a, b) \
    asm("fma.rn.f32x2 %0, %1, %2, %0;" : "+l"(acc) : "l"(a), "l"(b))
#define ADD2(d, a, b) \
    asm("add.rn.f32x2 %0, %1, %2;" : "=l"(d) : "l"(a), "l"(b))

__device__ __forceinline__ uint32_t smem_u32(const void* p) {
    uint32_t a;
    asm("{ .reg .u64 t; cvta.to.shared.u64 t, %1; cvt.u32.u64 %0, t; }" : "=r"(a) : "l"(p));
    return a;
}

#define MBAR_INIT(addr, cnt) \
    asm volatile("mbarrier.init.shared.b64 [%0], %1;" :: "r"(addr), "r"(cnt) : "memory")
#define MBAR_EXPECT_TX(addr, bytes) \
    asm volatile("mbarrier.arrive.expect_tx.shared.b64 _, [%0], %1;" :: "r"(addr), "r"(bytes) : "memory")
#define MBAR_ARRIVE(addr) \
    asm volatile("mbarrier.arrive.shared.b64 _, [%0];" :: "r"(addr) : "memory")
#define MBAR_WAIT(addr, parity) do {                                             \
    asm volatile("{\n\t.reg .pred P;\n"                                          \
        "W_%=:\n\tmbarrier.try_wait.parity.acquire.cta.shared::cta.b64 P, [%0], %1, 0x989680;\n" \
        "\t@P bra D_%=;\n\tbra W_%=;\nD_%=:\n\t}"                                \
        :: "r"(addr), "r"(parity) : "memory"); } while (0)

// plain contiguous bulk copy: gmem -> smem, completes on mbarrier
__device__ __forceinline__ void bulk_g2s(uint32_t dst, const void* src,
                                         uint32_t bytes, uint32_t mbar) {
    asm volatile(
        "cp.async.bulk.shared::cta.global.mbarrier::complete_tx::bytes "
        "[%0], [%1], %2, [%3];"
        :: "r"(dst), "l"(src), "r"(bytes), "r"(mbar) : "memory");
}

// fire-and-forget DRAM -> L2 prefetch (no SM-side tracking)
__device__ __forceinline__ void bulk_prefetch_l2(const void* src, uint32_t bytes) {
    asm volatile("cp.async.bulk.prefetch.L2.global [%0], %1;"
                 :: "l"(src), "r"(bytes) : "memory");
}

__device__ __forceinline__ void prefetch_chunk(const char* base) {
    #pragma unroll
    for (int q = 0; q < 4; q++)
        bulk_prefetch_l2(base + q * 16384, 16384);
}

__global__ void __launch_bounds__(NTHREADS, 1)
kdtree_router_kernel(const float* __restrict__ x,
                     const float* __restrict__ mean,
                     const float* __restrict__ comp,
                     const float* __restrict__ cent,
                     float* __restrict__ out)
{
    extern __shared__ __align__(1024) char smem_c[];
    float* part    = (float*)(smem_c + PART_OFF);   // [(TPB+1)*NP][32]
    float* cent_s  = (float*)(smem_c + CENT_OFF);
    float* centn_s = (float*)(smem_c + CENTN_OFF);
    const uint32_t mb = smem_u32(smem_c + MBAR_OFF);
    const uint32_t xs = smem_u32(smem_c + XS_OFF);

    const int tid  = threadIdx.x;
    const int lane = tid & 31;
    const int warp = tid >> 5;

    if (tid == 0) {
        #pragma unroll
        for (int s = 0; s < STAGES; s++) {
            MBAR_INIT(mb + s * 8, 1);               // full: expect_tx only
            MBAR_INIT(mb + 16 + s * 8, CWARPS);     // empty: 16 warp arrivals
        }
    }
    // centroids
    for (int i = tid; i < NE * NP; i += NTHREADS) cent_s[i] = cent[i];
    __syncthreads();

    const char* xbase = (const char*)x + (size_t)blockIdx.x * TPB * HD * 4;

    if (warp == PROD_WARP) {
        // ======================= producer =======================
        if (lane == 0) {
            // kick off copies for stages 0..1, prefetch 2..3
            #pragma unroll
            for (int c = 0; c < STAGES; c++) {
                MBAR_EXPECT_TX(mb + c * 8, (uint32_t)STAGE_BYTES);
                bulk_g2s(xs + c * STAGE_BYTES, xbase + (size_t)c * STAGE_BYTES,
                         STAGE_BYTES, mb + c * 8);
            }
            #pragma unroll
            for (int c = STAGES; c < STAGES + PDIST && c < NCHUNK; c++)
                prefetch_chunk(xbase + (size_t)c * STAGE_BYTES);

            #pragma unroll 1
            for (int c = STAGES; c < NCHUNK; c++) {
                int pf = c + PDIST;
                if (pf < NCHUNK)
                    prefetch_chunk(xbase + (size_t)pf * STAGE_BYTES);
                int s = c & 1, u = c >> 1;
                MBAR_WAIT(mb + 16 + s * 8, (u & 1) ^ 1);
                MBAR_EXPECT_TX(mb + s * 8, (uint32_t)STAGE_BYTES);
                bulk_g2s(xs + s * STAGE_BYTES, xbase + (size_t)c * STAGE_BYTES,
                         STAGE_BYTES, mb + s * 8);
            }
        }
        __syncthreads();   // match consumers' pre-epilogue barrier
        return;
    }

    // ======================= consumers =======================
    // comp slice -> registers: lane holds cols {4l..4l+3} and {128+4l..128+4l+3}
    ulonglong2 cA[NP], cB[NP];
    {
        const ulonglong2* cp0 = (const ulonglong2*)(comp + warp * SLICE);
        #pragma unroll
        for (int p = 0; p < NP; p++) {
            cA[p] = cp0[(size_t)p * (HD/4) + lane];
            cB[p] = cp0[(size_t)p * (HD/4) + lane + 32];
        }
    }

    // mean projection partials (pseudo-token TPB), same reduce path as tokens
    {
        const ulonglong2* mp = (const ulonglong2*)(mean + warp * SLICE);
        ulonglong2 ma = mp[lane], mbv = mp[lane + 32];
        unsigned long long acc[NP];
        #pragma unroll
        for (int p = 0; p < NP; p++) {
            acc[p] = 0ull;
            FMA2(acc[p], ma.x,  cA[p].x); FMA2(acc[p], ma.y,  cA[p].y);
            FMA2(acc[p], mbv.x, cB[p].x); FMA2(acc[p], mbv.y, cB[p].y);
        }
        unsigned long long u[3];
        #pragma unroll
        for (int j = 0; j < 3; j++) {
            float f0 = __uint_as_float((unsigned)(acc[2*j]   & 0xffffffffull)) +
                       __uint_as_float((unsigned)(acc[2*j]   >> 32));
            float f1 = __uint_as_float((unsigned)(acc[2*j+1] & 0xffffffffull)) +
                       __uint_as_float((unsigned)(acc[2*j+1] >> 32));
            u[j] = ((unsigned long long)__float_as_uint(f1) << 32) | __float_as_uint(f0);
        }
        #pragma unroll
        for (int o = 16; o >= 2; o >>= 1) {
            #pragma unroll
            for (int j = 0; j < 3; j++) {
                unsigned long long v = __shfl_xor_sync(0xffffffffu, u[j], o);
                ADD2(u[j], u[j], v);
            }
        }
        if (lane < 2) {
            int slot = warp * 2 + lane;
            #pragma unroll
            for (int j = 0; j < 3; j++) {
                part[(TPB*NP + 2*j  )*32 + slot] = __uint_as_float((unsigned)(u[j] & 0xffffffffull));
                part[(TPB*NP + 2*j+1)*32 + slot] = __uint_as_float((unsigned)(u[j] >> 32));
            }
        }
    }
    // centroid norms
    if (tid < NE) {
        float s = 0.f;
        #pragma unroll
        for (int p = 0; p < NP; p++) { float c = cent_s[tid*NP + p]; s += c * c; }
        centn_s[tid] = s;
    }

    // -------- main loop: 16 chunks x 4 tokens --------
    #pragma unroll 1
    for (int c = 0; c < NCHUNK; c++) {
        int s = c & 1, ph = (c >> 1) & 1;
        MBAR_WAIT(mb + s * 8, ph);

        #pragma unroll
        for (int t = 0; t < STAGE_TOK; t++) {
            const ulonglong2* xp = (const ulonglong2*)
                (smem_c + XS_OFF + s * STAGE_BYTES + t * (HD*4) + warp * (SLICE*4));
            ulonglong2 xa = xp[lane];
            ulonglong2 xb = xp[lane + 32];

            unsigned long long acc[NP];
            #pragma unroll
            for (int p = 0; p < NP; p++) {
                acc[p] = 0ull;
                FMA2(acc[p], xa.x, cA[p].x); FMA2(acc[p], xa.y, cA[p].y);
                FMA2(acc[p], xb.x, cB[p].x); FMA2(acc[p], xb.y, cB[p].y);
            }
            unsigned long long u[3];
            #pragma unroll
            for (int j = 0; j < 3; j++) {
                float f0 = __uint_as_float((unsigned)(acc[2*j]   & 0xffffffffull)) +
                           __uint_as_float((unsigned)(acc[2*j]   >> 32));
                float f1 = __uint_as_float((unsigned)(acc[2*j+1] & 0xffffffffull)) +
                           __uint_as_float((unsigned)(acc[2*j+1] >> 32));
                u[j] = ((unsigned long long)__float_as_uint(f1) << 32) | __float_as_uint(f0);
            }
            #pragma unroll
            for (int o = 16; o >= 2; o >>= 1) {
                #pragma unroll
                for (int j = 0; j < 3; j++) {
                    unsigned long long v = __shfl_xor_sync(0xffffffffu, u[j], o);
                    ADD2(u[j], u[j], v);
                }
            }
            if (lane < 2) {
                int tok = c * STAGE_TOK + t;
                int slot = warp * 2 + lane;
                #pragma unroll
                for (int j = 0; j < 3; j++) {
                    part[(tok*NP + 2*j  )*32 + slot] = __uint_as_float((unsigned)(u[j] & 0xffffffffull));
                    part[(tok*NP + 2*j+1)*32 + slot] = __uint_as_float((unsigned)(u[j] >> 32));
                }
            }
        }
        __syncwarp();
        if (lane == 0) MBAR_ARRIVE(mb + 16 + s * 8);
    }

    __syncthreads();   // all partials visible

    // -------- epilogue: warp handles 4 tokens --------
    float mpj[NP];
    #pragma unroll
    for (int p = 0; p < NP; p++) {
        float v = part[(TPB*NP + p)*32 + lane];
        #pragma unroll
        for (int o = 16; o > 0; o >>= 1)
            v += __shfl_xor_sync(0xffffffffu, v, o);
        mpj[p] = v;
    }

    float* out_idx = out;
    float* out_tp  = out + (size_t)NTOK * TK;
    float* out_pr  = out + 2 * (size_t)NTOK * TK;

    #pragma unroll 1
    for (int t = 0; t < 4; t++) {
        const int ltok = warp * 4 + t;
        const int tok  = blockIdx.x * TPB + ltok;

        float pr[NP];
        #pragma unroll
        for (int p = 0; p < NP; p++) {
            float v = part[(ltok*NP + p)*32 + lane];
            #pragma unroll
            for (int o = 16; o > 0; o >>= 1)
                v += __shfl_xor_sync(0xffffffffu, v, o);
            pr[p] = v - mpj[p];
        }
        float pn = 0.f;
        #pragma unroll
        for (int p = 0; p < NP; p++) pn += pr[p] * pr[p];

        const int e0 = lane, e1 = lane + 32;
        float dot0 = 0.f, dot1 = 0.f;
        #pragma unroll
        for (int p = 0; p < NP; p++) {
            dot0 += pr[p] * cent_s[e0*NP + p];
            dot1 += pr[p] * cent_s[e1*NP + p];
        }
        float d20 = pn - 2.f*dot0 + centn_s[e0];
        float d21 = pn - 2.f*dot1 + centn_s[e1];
        float s0 = -sqrtf(fmaxf(d20, 0.f));
        float s1 = -sqrtf(fmaxf(d21, 0.f));

        float m = fmaxf(s0, s1);
        #pragma unroll
        for (int o = 16; o > 0; o >>= 1)
            m = fmaxf(m, __shfl_xor_sync(0xffffffffu, m, o));
        float ex0 = expf(s0 - m);
        float ex1 = expf(s1 - m);
        float sum = ex0 + ex1;
        #pragma unroll
        for (int o = 16; o > 0; o >>= 1)
            sum += __shfl_xor_sync(0xffffffffu, sum, o);
        float p0 = ex0 / sum;
        float p1 = ex1 / sum;

        out_pr[(size_t)tok*NE + e0] = p0;
        out_pr[(size_t)tok*NE + e1] = p1;

        // top-8 via 8-round warp argmax; tie-break = lower index
        unsigned long long k0 = ((unsigned long long)__float_as_uint(p0) << 32) | (unsigned)(NE-1 - e0);
        unsigned long long k1 = ((unsigned long long)__float_as_uint(p1) << 32) | (unsigned)(NE-1 - e1);
        float tsum = 0.f, myp = 0.f;
        int myi = 0;
        #pragma unroll
        for (int r = 0; r < TK; r++) {
            unsigned long long b = (k0 > k1) ? k0 : k1;
            #pragma unroll
            for (int o = 16; o > 0; o >>= 1) {
                unsigned long long v = __shfl_xor_sync(0xffffffffu, b, o);
                if (v > b) b = v;
            }
            int idx = NE-1 - (int)(b & 0xffull);
            float pv = __uint_as_float((unsigned)(b >> 32));
            tsum += pv;
            if (lane == r) { myp = pv; myi = idx; }
            if (idx == e0) k0 = 0ull;
            if (idx == e1) k1 = 0ull;
        }
        if (lane < TK) {
            out_idx[(size_t)tok*TK + lane] = (float)myi;
            out_tp [(size_t)tok*TK + lane] = myp / tsum;
        }
    }
}

extern "C" void kernel_launch(void* const* d_in, const int* in_sizes, int n_in,
                              void* d_out, int out_size)
{
    const float* x    = (const float*)d_in[0];
    const float* mean = (const float*)d_in[1];
    const float* comp = (const float*)d_in[2];
    const float* cent = (const float*)d_in[3];
    float* out = (float*)d_out;

    cudaFuncSetAttribute(kdtree_router_kernel,
                         cudaFuncAttributeMaxDynamicSharedMemorySize, SMEM_BYTES);
    kdtree_router_kernel<<<NTOK / TPB, NTHREADS, SMEM_BYTES>>>(x, mean, comp, cent, out);
}

// round 7
// speedup vs baseline: 1.2172x; 1.1241x over previous
#include <cuda_runtime.h>
#include <stdint.h>
#include <math.h>

#define NTOK 16384
#define HD   4096
#define NE   64
#define NP   6
#define TK   8

#define CWARPS   16                     // consumer warps (one 256-col slice each)
#define NTHREADS ((CWARPS + 1) * 32)    // 544
#define PROD_WARP CWARPS
#define SLICE    (HD / CWARPS)          // 256

#define UNIT_TOK  16
#define NUNITS    (NTOK / UNIT_TOK)     // 1024
#define STAGE_TOK 2
#define STAGE_BYTES (STAGE_TOK * HD * 4)   // 32768
#define STAGES    4
#define CPU       (UNIT_TOK / STAGE_TOK)   // 8 chunks per unit
#define GRID      148

// smem byte offsets
#define XS_OFF    0
#define PART_OFF  (STAGES * STAGE_BYTES)                 // 131072
#define PART_SZ   ((UNIT_TOK + 1) * NP * 32 * 4)         // 13056 (row 16*NP.. = mean)
#define CENT_OFF  (PART_OFF + PART_SZ)
#define CENTN_OFF (CENT_OFF + NE * NP * 4)
#define UID_OFF   (CENTN_OFF + NE * 4)
#define MBAR_OFF  (UID_OFF + 16)                          // 8-aligned
#define SMEM_BYTES (MBAR_OFF + 64)

__device__ unsigned g_unit_ctr;

#define FMA2(acc, a, b) \
    asm("fma.rn.f32x2 %0, %1, %2, %0;" : "+l"(acc) : "l"(a), "l"(b))
#define ADD2(d, a, b) \
    asm("add.rn.f32x2 %0, %1, %2;" : "=l"(d) : "l"(a), "l"(b))

__device__ __forceinline__ uint32_t smem_u32(const void* p) {
    uint32_t a;
    asm("{ .reg .u64 t; cvta.to.shared.u64 t, %1; cvt.u32.u64 %0, t; }" : "=r"(a) : "l"(p));
    return a;
}

#define MBAR_INIT(addr, cnt) \
    asm volatile("mbarrier.init.shared.b64 [%0], %1;" :: "r"(addr), "r"(cnt) : "memory")
#define MBAR_EXPECT_TX(addr, bytes) \
    asm volatile("mbarrier.arrive.expect_tx.shared.b64 _, [%0], %1;" :: "r"(addr), "r"(bytes) : "memory")
#define MBAR_ARRIVE(addr) \
    asm volatile("mbarrier.arrive.shared.b64 _, [%0];" :: "r"(addr) : "memory")
#define MBAR_WAIT(addr, parity) do {                                             \
    asm volatile("{\n\t.reg .pred P;\n"                                          \
        "W_%=:\n\tmbarrier.try_wait.parity.acquire.cta.shared::cta.b64 P, [%0], %1, 0x989680;\n" \
        "\t@P bra D_%=;\n\tbra W_%=;\nD_%=:\n\t}"                                \
        :: "r"(addr), "r"(parity) : "memory"); } while (0)

__device__ __forceinline__ void bulk_g2s(uint32_t dst, const void* src,
                                         uint32_t bytes, uint32_t mbar) {
    asm volatile(
        "cp.async.bulk.shared::cta.global.mbarrier::complete_tx::bytes "
        "[%0], [%1], %2, [%3];"
        :: "r"(dst), "l"(src), "r"(bytes), "r"(mbar) : "memory");
}

#define CBAR() asm volatile("bar.sync 1, 512;" ::: "memory")

__global__ void reset_ctr_kernel() { g_unit_ctr = 0u; }

__global__ void __launch_bounds__(NTHREADS, 1)
kdtree_router_kernel(const float* __restrict__ x,
                     const float* __restrict__ mean,
                     const float* __restrict__ comp,
                     const float* __restrict__ cent,
                     float* __restrict__ out)
{
    extern __shared__ __align__(1024) char smem_c[];
    float* part    = (float*)(smem_c + PART_OFF);
    float* cent_s  = (float*)(smem_c + CENT_OFF);
    float* centn_s = (float*)(smem_c + CENTN_OFF);
    unsigned* uid  = (unsigned*)(smem_c + UID_OFF);
    const uint32_t mb = smem_u32(smem_c + MBAR_OFF);
    const uint32_t xs = smem_u32(smem_c + XS_OFF);

    const int tid  = threadIdx.x;
    const int lane = tid & 31;
    const int warp = tid >> 5;

    if (tid == 0) {
        #pragma unroll
        for (int s = 0; s < STAGES; s++) {
            MBAR_INIT(mb + s * 8, 1);               // full: expect_tx arrive
            MBAR_INIT(mb + 32 + s * 8, CWARPS);     // empty: 16 warp arrivals
        }
    }
    for (int i = tid; i < NE * NP; i += NTHREADS) cent_s[i] = cent[i];
    __syncthreads();

    // ---------- per-CTA prologue ----------
    ulonglong2 cA[NP], cB[NP];
    if (warp < CWARPS) {
        const ulonglong2* cp0 = (const ulonglong2*)(comp + warp * SLICE);
        #pragma unroll
        for (int p = 0; p < NP; p++) {
            cA[p] = cp0[(size_t)p * (HD/4) + lane];
            cB[p] = cp0[(size_t)p * (HD/4) + lane + 32];
        }
        // mean projection partials -> part row UNIT_TOK
        const ulonglong2* mp = (const ulonglong2*)(mean + warp * SLICE);
        ulonglong2 ma = mp[lane], mbv = mp[lane + 32];
        unsigned long long acc[NP];
        #pragma unroll
        for (int p = 0; p < NP; p++) {
            acc[p] = 0ull;
            FMA2(acc[p], ma.x,  cA[p].x); FMA2(acc[p], ma.y,  cA[p].y);
            FMA2(acc[p], mbv.x, cB[p].x); FMA2(acc[p], mbv.y, cB[p].y);
        }
        unsigned long long u[3];
        #pragma unroll
        for (int j = 0; j < 3; j++) {
            float f0 = __uint_as_float((unsigned)(acc[2*j]   & 0xffffffffull)) +
                       __uint_as_float((unsigned)(acc[2*j]   >> 32));
            float f1 = __uint_as_float((unsigned)(acc[2*j+1] & 0xffffffffull)) +
                       __uint_as_float((unsigned)(acc[2*j+1] >> 32));
            u[j] = ((unsigned long long)__float_as_uint(f1) << 32) | __float_as_uint(f0);
        }
        #pragma unroll
        for (int o = 16; o >= 2; o >>= 1)
            #pragma unroll
            for (int j = 0; j < 3; j++) {
                unsigned long long v = __shfl_xor_sync(0xffffffffu, u[j], o);
                ADD2(u[j], u[j], v);
            }
        if (lane < 2) {
            int slot = warp * 2 + lane;
            #pragma unroll
            for (int j = 0; j < 3; j++) {
                part[(UNIT_TOK*NP + 2*j  )*32 + slot] = __uint_as_float((unsigned)(u[j] & 0xffffffffull));
                part[(UNIT_TOK*NP + 2*j+1)*32 + slot] = __uint_as_float((unsigned)(u[j] >> 32));
            }
        }
        if (tid < NE) {
            float s = 0.f;
            #pragma unroll
            for (int p = 0; p < NP; p++) { float c = cent_s[tid*NP + p]; s += c * c; }
            centn_s[tid] = s;
        }
    }
    __syncthreads();

    if (warp == PROD_WARP) {
        // ======================= producer =======================
        if (lane == 0) {
            unsigned pc = 0;
            for (;;) {
                unsigned un = atomicAdd(&g_unit_ctr, 1u);
                if (un >= NUNITS) break;
                const char* ubase = (const char*)x + (size_t)un * UNIT_TOK * HD * 4;
                #pragma unroll 1
                for (int ci = 0; ci < CPU; ci++) {
                    int s = pc & (STAGES - 1);
                    unsigned up = pc >> 2;
                    if (pc >= STAGES) MBAR_WAIT(mb + 32 + s * 8, (up & 1) ^ 1);
                    uid[s] = un * UNIT_TOK + ci * STAGE_TOK;
                    MBAR_EXPECT_TX(mb + s * 8, (uint32_t)STAGE_BYTES);
                    bulk_g2s(xs + s * STAGE_BYTES, ubase + (size_t)ci * STAGE_BYTES,
                             STAGE_BYTES, mb + s * 8);
                    pc++;
                }
            }
            // sentinel
            int s = pc & (STAGES - 1);
            unsigned up = pc >> 2;
            if (pc >= STAGES) MBAR_WAIT(mb + 32 + s * 8, (up & 1) ^ 1);
            uid[s] = 0xFFFFFFFFu;
            MBAR_ARRIVE(mb + s * 8);
        }
        return;
    }

    // ======================= consumers =======================
    float mpj[NP];
    #pragma unroll
    for (int p = 0; p < NP; p++) {
        float v = part[(UNIT_TOK*NP + p)*32 + lane];
        #pragma unroll
        for (int o = 16; o > 0; o >>= 1)
            v += __shfl_xor_sync(0xffffffffu, v, o);
        mpj[p] = v;
    }

    float* out_idx = out;
    float* out_tp  = out + (size_t)NTOK * TK;
    float* out_pr  = out + 2 * (size_t)NTOK * TK;

    unsigned pc = 0;
    for (;;) {
        int s = pc & (STAGES - 1);
        unsigned up = pc >> 2;
        MBAR_WAIT(mb + s * 8, up & 1);
        unsigned tokbase = uid[s];
        if (tokbase == 0xFFFFFFFFu) break;

        #pragma unroll
        for (int t = 0; t < STAGE_TOK; t++) {
            const ulonglong2* xp = (const ulonglong2*)
                (smem_c + XS_OFF + s * STAGE_BYTES + t * (HD*4) + warp * (SLICE*4));
            ulonglong2 xa = xp[lane];
            ulonglong2 xb = xp[lane + 32];

            unsigned long long acc[NP];
            #pragma unroll
            for (int p = 0; p < NP; p++) {
                acc[p] = 0ull;
                FMA2(acc[p], xa.x, cA[p].x); FMA2(acc[p], xa.y, cA[p].y);
                FMA2(acc[p], xb.x, cB[p].x); FMA2(acc[p], xb.y, cB[p].y);
            }
            unsigned long long u[3];
            #pragma unroll
            for (int j = 0; j < 3; j++) {
                float f0 = __uint_as_float((unsigned)(acc[2*j]   & 0xffffffffull)) +
                           __uint_as_float((unsigned)(acc[2*j]   >> 32));
                float f1 = __uint_as_float((unsigned)(acc[2*j+1] & 0xffffffffull)) +
                           __uint_as_float((unsigned)(acc[2*j+1] >> 32));
                u[j] = ((unsigned long long)__float_as_uint(f1) << 32) | __float_as_uint(f0);
            }
            #pragma unroll
            for (int o = 16; o >= 2; o >>= 1)
                #pragma unroll
                for (int j = 0; j < 3; j++) {
                    unsigned long long v = __shfl_xor_sync(0xffffffffu, u[j], o);
                    ADD2(u[j], u[j], v);
                }
            if (lane < 2) {
                int ltok = (int)(tokbase & 15u) + t;
                int slot = warp * 2 + lane;
                #pragma unroll
                for (int j = 0; j < 3; j++) {
                    part[(ltok*NP + 2*j  )*32 + slot] = __uint_as_float((unsigned)(u[j] & 0xffffffffull));
                    part[(ltok*NP + 2*j+1)*32 + slot] = __uint_as_float((unsigned)(u[j] >> 32));
                }
            }
        }
        __syncwarp();
        if (lane == 0) MBAR_ARRIVE(mb + 32 + s * 8);
        pc++;

        if ((tokbase & 15u) == (UNIT_TOK - STAGE_TOK)) {
            // last chunk of a 16-token unit -> epilogue (warp w = token w)
            CBAR();
            const unsigned tok = (tokbase & ~15u) + warp;

            float pr[NP];
            #pragma unroll
            for (int p = 0; p < NP; p++) {
                float v = part[(warp*NP + p)*32 + lane];
                #pragma unroll
                for (int o = 16; o > 0; o >>= 1)
                    v += __shfl_xor_sync(0xffffffffu, v, o);
                pr[p] = v - mpj[p];
            }
            float pn = 0.f;
            #pragma unroll
            for (int p = 0; p < NP; p++) pn += pr[p] * pr[p];

            const int e0 = lane, e1 = lane + 32;
            float dot0 = 0.f, dot1 = 0.f;
            #pragma unroll
            for (int p = 0; p < NP; p++) {
                dot0 += pr[p] * cent_s[e0*NP + p];
                dot1 += pr[p] * cent_s[e1*NP + p];
            }
            float d20 = pn - 2.f*dot0 + centn_s[e0];
            float d21 = pn - 2.f*dot1 + centn_s[e1];
            float s0 = -sqrtf(fmaxf(d20, 0.f));
            float s1 = -sqrtf(fmaxf(d21, 0.f));

            float m = fmaxf(s0, s1);
            #pragma unroll
            for (int o = 16; o > 0; o >>= 1)
                m = fmaxf(m, __shfl_xor_sync(0xffffffffu, m, o));
            float ex0 = expf(s0 - m);
            float ex1 = expf(s1 - m);
            float sum = ex0 + ex1;
            #pragma unroll
            for (int o = 16; o > 0; o >>= 1)
                sum += __shfl_xor_sync(0xffffffffu, sum, o);
            float p0 = ex0 / sum;
            float p1 = ex1 / sum;

            out_pr[(size_t)tok*NE + e0] = p0;
            out_pr[(size_t)tok*NE + e1] = p1;

            // top-8 via 8-round warp argmax; tie-break = lower index
            unsigned long long k0 = ((unsigned long long)__float_as_uint(p0) << 32) | (unsigned)(NE-1 - e0);
            unsigned long long k1 = ((unsigned long long)__float_as_uint(p1) << 32) | (unsigned)(NE-1 - e1);
            float tsum = 0.f, myp = 0.f;
            int myi = 0;
            #pragma unroll
            for (int r = 0; r < TK; r++) {
                unsigned long long b = (k0 > k1) ? k0 : k1;
                #pragma unroll
                for (int o = 16; o > 0; o >>= 1) {
                    unsigned long long v = __shfl_xor_sync(0xffffffffu, b, o);
                    if (v > b) b = v;
                }
                int idx = NE-1 - (int)(b & 0xffull);
                float pv = __uint_as_float((unsigned)(b >> 32));
                tsum += pv;
                if (lane == r) { myp = pv; myi = idx; }
                if (idx == e0) k0 = 0ull;
                if (idx == e1) k1 = 0ull;
            }
            if (lane < TK) {
                out_idx[(size_t)tok*TK + lane] = (float)myi;
                out_tp [(size_t)tok*TK + lane] = myp / tsum;
            }
            CBAR();   // protect part[] before next unit overwrites
        }
    }
}

extern "C" void kernel_launch(void* const* d_in, const int* in_sizes, int n_in,
                              void* d_out, int out_size)
{
    const float* x    = (const float*)d_in[0];
    const float* mean = (const float*)d_in[1];
    const float* comp = (const float*)d_in[2];
    const float* cent = (const float*)d_in[3];
    float* out = (float*)d_out;

    reset_ctr_kernel<<<1, 1>>>();
    cudaFuncSetAttribute(kdtree_router_kernel,
                         cudaFuncAttributeMaxDynamicSharedMemorySize, SMEM_BYTES);
    kdtree_router_kernel<<<GRID, NTHREADS, SMEM_BYTES>>>(x, mean, comp, cent, out);
}